// round 16
// baseline (speedup 1.0000x reference)
#include <cuda_runtime.h>
#include <cuda_fp16.h>
#include <cstdint>

// ---------------- problem constants ----------------
namespace {
constexpr int Bv = 128, Lv = 64, Tv = 20, Vv = 32000;
constexpr int Ev = 512, Hv = 1024, Av = 512, Fv = 2048;
constexpr int G4H = 4 * Hv;          // 4096
constexpr int CAT = Fv + Hv;         // 3072 : [ctx | h]
constexpr int S_XD = 8, S_GT = 4, S_HC = 4;
constexpr int LDT = 40;              // smem leading dim (fp16), conflict-free pad
constexpr int NBLK = 128;            // loop blocks
constexpr int NFUSE = 148;           // fused grid
constexpr int THR = 512;             // threads per fused block
constexpr int NT_N = Vv / 256;       // 125 logits n-tiles (256 wide)
constexpr int NTILES = Tv * NT_N;    // 2500 logits tiles
constexpr int SK_TILES = 2 * S_HC * (Hv / 32);  // 256 h0/c0 split-K tiles
// preproc merged GEMM
constexpr int PRE_XENC = (Bv * Lv / 128) * (Av / 128);   // 256
constexpr int PRE_EMBG = (Tv * Bv / 128) * (G4H / 128);  // 640
// big logits tile: 128x256, 3-stage
constexpr int BIG_STG = (128 + 256) * LDT;
constexpr int BIG_OFFB = 128 * LDT;
constexpr int SMEM_BIG = 3 * BIG_STG * 2;         // 92160 bytes
constexpr int SMEM_P1 = 2 * (2 * 128 * LDT) * 2;  // 40960 (preproc gemms)
// mma128_tile: 3 stages x (A0,B0,A1,B1) regions of 128*LDT halfs
constexpr int M128_REG = 128 * LDT;
constexpr int M128_STG = 4 * M128_REG;
constexpr int SMEM_FUSED = 3 * M128_STG * 2;      // 122880 bytes (covers logits 92160)
}

// ---------------- scratch (device globals) ----------------
__device__ float g_mean[Bv * Fv];
__device__ float g_c[Bv * Hv];
__device__ float g_embgate[(size_t)Tv * Bv * G4H];
__device__ float g_xdp[(size_t)S_XD * Bv * Av];
__device__ float g_gatep[(size_t)S_GT * Bv * G4H];
__device__ float g_hp[(size_t)S_HC * Bv * Hv];
__device__ float g_cp[(size_t)S_HC * Bv * Hv];
__device__ unsigned g_bar;
__device__ unsigned g_tile;
__device__ unsigned g_tdone;
// fp16 operands
__device__ __half g_Xhi[(size_t)Bv * Lv * Fv];
__device__ __half g_xench[(size_t)Bv * Lv * Av];
__device__ __half g_embxhi[(size_t)Tv * Bv * Ev];
__device__ __half g_cathi[(size_t)Bv * CAT];
__device__ __half g_Hallhi[(size_t)Tv * Bv * Hv];
__device__ __half g_owThi[(size_t)Vv * Hv];
__device__ __half g_WcatThi[(size_t)G4H * CAT];
__device__ __half g_fc2Thi[(size_t)Av * Fv];
__device__ __half g_wihEThi[(size_t)G4H * Ev];
__device__ __half g_fc1Thi[(size_t)Av * Hv];

__device__ __forceinline__ float sigmoidf_(float x) { return 1.0f / (1.0f + expf(-x)); }

__device__ __forceinline__ float rcp_fast(float d) {
    float r = __int_as_float(0x7EF311C3 - __float_as_int(d));
    r = r * (2.0f - d * r);
    r = r * (2.0f - d * r);
    return r;
}
__device__ __forceinline__ float tanh_fast(float x) {
    x = fminf(fmaxf(x, -4.97f), 4.97f);
    float x2 = x * x;
    float num = x * (135135.f + x2 * (17325.f + x2 * (378.f + x2)));
    float den = 135135.f + x2 * (62370.f + x2 * (3150.f + x2 * 28.f));
    return num * rcp_fast(den);
}

// ---------------- PTX helpers ----------------
__device__ __forceinline__ uint32_t smem_u32(const void* p) {
    uint32_t a;
    asm("{ .reg .u64 t; cvta.to.shared.u64 t, %1; cvt.u32.u64 %0, t; }" : "=r"(a) : "l"(p));
    return a;
}
__device__ __forceinline__ void cp16(uint32_t s, const void* g) {
    asm volatile("cp.async.cg.shared.global [%0], [%1], 16;" :: "r"(s), "l"(g));
}
__device__ __forceinline__ void ldsm4(uint32_t& r0, uint32_t& r1, uint32_t& r2,
                                      uint32_t& r3, uint32_t a) {
    asm volatile("ldmatrix.sync.aligned.m8n8.x4.shared.b16 {%0,%1,%2,%3}, [%4];"
                 : "=r"(r0), "=r"(r1), "=r"(r2), "=r"(r3) : "r"(a));
}
__device__ __forceinline__ void mma16816(float* c, const uint32_t* a, const uint32_t* b) {
    asm volatile(
        "mma.sync.aligned.m16n8k16.row.col.f32.f16.f16.f32 "
        "{%0,%1,%2,%3}, {%4,%5,%6,%7}, {%8,%9}, {%0,%1,%2,%3};"
        : "+f"(c[0]), "+f"(c[1]), "+f"(c[2]), "+f"(c[3])
        : "r"(a[0]), "r"(a[1]), "r"(a[2]), "r"(a[3]), "r"(b[0]), "r"(b[1]));
}

// grid barrier among the NBLK loop blocks (round-13 proven form)
__device__ __forceinline__ void gridbar(unsigned& tgt) {
    __syncthreads();
    if (threadIdx.x == 0) {
        tgt += NBLK;
        __threadfence();
        atomicAdd(&g_bar, 1u);
        unsigned v;
        do {
            asm volatile("ld.acquire.gpu.u32 %0, [%1];" : "=r"(v) : "l"(&g_bar) : "memory");
            if (v >= tgt) break;
            __nanosleep(32);
        } while (true);
    }
    __syncthreads();
}

// ---------------- prep_all: counters + convX + mean + gather + ALL transposes ----------------
// transpose tiles are 32(k) x 128(n), float4 loads, 2x16B transposed stores.
__global__ void prep_all(const float* __restrict__ X, const void* __restrict__ yraw,
                         const float* __restrict__ emb,
                         const float* __restrict__ out_w,
                         const float* __restrict__ w_ih,
                         const float* __restrict__ w_hh,
                         const float* __restrict__ fc2_w,
                         const float* __restrict__ fc1_w) {
    constexpr int NCVX = (Bv * Lv * Fv) / 4 / 256;   // 16384
    constexpr int NMEAN = (Bv * Fv) / 256;           // 1024
    constexpr int NGATH = (Tv * Bv * Ev) / 256;      // 2560
    constexpr int B0 = NCVX, B1 = B0 + NMEAN, B2 = B1 + NGATH;
    constexpr int TOW = (Hv / 32) * (Vv / 128);      // 8000
    constexpr int TWC = (CAT / 32) * (G4H / 128);    // 3072
    constexpr int TF2 = (Fv / 32) * (Av / 128);      // 256
    constexpr int TWE = (Ev / 32) * (G4H / 128);     // 512
    constexpr int B3 = B2 + TOW, B4 = B3 + TWC, B5 = B4 + TF2, B6 = B5 + TWE;
    const int bid = blockIdx.x;
    const int tid = threadIdx.x;
    if (bid == 0 && tid == 0) { g_bar = 0; g_tile = 0; g_tdone = 0; }
    if (bid < B0) {
        size_t i = (size_t)bid * 256 + tid;
        float4 v = ((const float4*)X)[i];
        __half2* o = reinterpret_cast<__half2*>(g_Xhi) + 2 * i;
        o[0] = __floats2half2_rn(v.x, v.y);
        o[1] = __floats2half2_rn(v.z, v.w);
        return;
    }
    if (bid < B1) {
        int idx = (bid - B0) * 256 + tid;
        int f = idx % Fv, b = idx / Fv;
        const float* Xb = X + (size_t)b * Lv * Fv + f;
        float s = 0.f;
#pragma unroll
        for (int l = 0; l < Lv; l++) s += Xb[(size_t)l * Fv];
        g_mean[idx] = s * (1.0f / Lv);
        return;
    }
    if (bid < B2) {
        __shared__ int ok;
        if (tid == 0) ok = 1;
        __syncthreads();
        const int* y32 = (const int*)yraw;
        for (int i = tid; i < (Bv * (Tv + 1)) / 2; i += 256)
            if (y32[2 * i + 1] != 0) ok = 0;
        __syncthreads();
        size_t idx = (size_t)(bid - B1) * 256 + tid;
        int e = (int)(idx % Ev);
        int r = (int)(idx / Ev);
        int b = r % Bv, t = r / Bv;
        int token;
        if (ok)
            token = (int)((const long long*)yraw)[(size_t)b * (Tv + 1) + t];
        else
            token = y32[(size_t)b * (Tv + 1) + t];
        g_embxhi[idx] = __float2half_rn(emb[(size_t)token * Ev + e]);
        return;
    }
    // ---- transposes: 32(k) x 128(n) tiles ----
    __shared__ float tile[32][129];
    const float *s1, *s2;
    int Ksplit, K, N;
    __half* dhi;
    int r, nc;
    if (bid < B3) {                          // out_w -> owThi [Vv, Hv]
        r = bid - B2;
        s1 = out_w; s2 = nullptr; Ksplit = Hv; K = Hv; N = Vv; dhi = g_owThi;
        nc = Vv / 128;
    } else if (bid < B4) {                   // [w_ih[E:]; w_hh] -> WcatThi [G4H, CAT]
        r = bid - B3;
        s1 = w_ih + (size_t)Ev * G4H; s2 = w_hh; Ksplit = Fv; K = CAT; N = G4H;
        dhi = g_WcatThi;
        nc = G4H / 128;
    } else if (bid < B5) {                   // fc2_w -> fc2Thi [Av, Fv]
        r = bid - B4;
        s1 = fc2_w; s2 = nullptr; Ksplit = Fv; K = Fv; N = Av; dhi = g_fc2Thi;
        nc = Av / 128;
    } else if (bid < B6) {                   // w_ih[:E] -> wihEThi [G4H, Ev]
        r = bid - B5;
        s1 = w_ih; s2 = nullptr; Ksplit = Ev; K = Ev; N = G4H; dhi = g_wihEThi;
        nc = G4H / 128;
    } else {                                 // fc1_w -> fc1Thi [Av, Hv]
        r = bid - B6;
        s1 = fc1_w; s2 = nullptr; Ksplit = Hv; K = Hv; N = Av; dhi = g_fc1Thi;
        nc = Av / 128;
    }
    const int n0 = (r % nc) * 128, k0 = (r / nc) * 32;
#pragma unroll
    for (int it = 0; it < 4; it++) {
        int i = tid + it * 256;
        int kr = i >> 5, c4 = i & 31;
        int k = k0 + kr;
        const float* s = (k < Ksplit) ? (s1 + (size_t)k * N)
                                      : (s2 + (size_t)(k - Ksplit) * N);
        float4 v = *reinterpret_cast<const float4*>(s + n0 + c4 * 4);
        tile[kr][c4 * 4 + 0] = v.x;
        tile[kr][c4 * 4 + 1] = v.y;
        tile[kr][c4 * 4 + 2] = v.z;
        tile[kr][c4 * 4 + 3] = v.w;
    }
    __syncthreads();
    {
        int n = tid >> 1, part = (tid & 1) * 16;
        __half h[16];
#pragma unroll
        for (int j = 0; j < 16; j++) h[j] = __float2half_rn(tile[part + j][n]);
        __half* dst = dhi + (size_t)(n0 + n) * K + k0 + part;
        *reinterpret_cast<uint4*>(dst) = *reinterpret_cast<uint4*>(h);
        *reinterpret_cast<uint4*>(dst + 8) = *reinterpret_cast<uint4*>(h + 8);
    }
}

// ---------------- SIMT split-K tile for h0/c0 (512 threads, device fn) ----------------
__device__ void sk_tile(char* smem, const float* __restrict__ Bw,
                        float* __restrict__ Part, int s, int bn0) {
    float* As = (float*)smem;           // [32][132]
    float* Bs = As + 32 * 132;          // [32][32]
    const int tid = threadIdx.x;
    const int tx = tid & 15, ty = tid >> 4;
    const int Ks = Fv / S_HC;
    const int kbeg = s * Ks;
    float acc[4][2] = {};
    for (int k0 = kbeg; k0 < kbeg + Ks; k0 += 32) {
#pragma unroll
        for (int it = 0; it < 8; it++) {
            int i = tid + it * THR;
            int r = i >> 5, c = i & 31;
            As[c * 132 + r] = g_mean[(size_t)r * Fv + k0 + c];
        }
#pragma unroll
        for (int it = 0; it < 2; it++) {
            int i = tid + it * THR;
            int r = i >> 5, c = i & 31;
            Bs[r * 32 + c] = Bw[(size_t)(k0 + r) * Hv + bn0 + c];
        }
        __syncthreads();
#pragma unroll
        for (int kk = 0; kk < 32; kk++) {
            float ar[4];
            float br0 = Bs[kk * 32 + tx * 2], br1 = Bs[kk * 32 + tx * 2 + 1];
            *reinterpret_cast<float4*>(ar) =
                *reinterpret_cast<const float4*>(&As[kk * 132 + ty * 4]);
#pragma unroll
            for (int i = 0; i < 4; i++) {
                acc[i][0] = fmaf(ar[i], br0, acc[i][0]);
                acc[i][1] = fmaf(ar[i], br1, acc[i][1]);
            }
        }
        __syncthreads();
    }
    float* P = Part + (size_t)s * 128 * Hv;
#pragma unroll
    for (int i = 0; i < 4; i++) {
        int r = ty * 4 + i;
        P[(size_t)r * Hv + bn0 + tx * 2] = acc[i][0];
        P[(size_t)r * Hv + bn0 + tx * 2 + 1] = acc[i][1];
    }
}

// ---------------- 128x128 1-pass fp16 mma tile, 512 threads, 3-stage, K64 chunks ----------------
__device__ void mma128_tile(char* smem,
                            const __half* __restrict__ A, int lda,
                            const __half* __restrict__ B, int ldb, int K,
                            float* __restrict__ C, int ldc,
                            int bm0, int bn0) {
    const int tid = threadIdx.x, lane = tid & 31, warp = tid >> 5;
    const int wm = warp & 3, wn = warp >> 2;   // 4(M) x 4(N) warps, each 32x32
    const uint32_t sbase = smem_u32(smem);
    float acc[2][4][4] = {};
    const int arow = ((lane >> 3) & 1) * 8 + (lane & 7);
    const int akof = (lane >> 4) * 8;
    const int brow = ((lane >> 4) & 1) * 8 + (lane & 7);
    const int bkof = ((lane >> 3) & 1) * 8;
    const int NKC = K / 64;

    auto issue = [&](int st, int kc) {
        const int k0 = kc * 64;
        int r = tid >> 2, sg = tid & 3;
        uint32_t so = sbase + (uint32_t)(st * M128_STG + r * LDT + sg * 8) * 2;
        const __half* Ap = A + (size_t)(bm0 + r) * lda + k0 + sg * 8;
        const __half* Bp = B + (size_t)(bn0 + r) * ldb + k0 + sg * 8;
        cp16(so, Ap);
        cp16(so + (uint32_t)M128_REG * 2, Bp);
        cp16(so + (uint32_t)(2 * M128_REG) * 2, Ap + 32);
        cp16(so + (uint32_t)(3 * M128_REG) * 2, Bp + 32);
        asm volatile("cp.async.commit_group;" ::: "memory");
    };

    issue(0, 0);
    if (NKC > 1) issue(1, 1);
#pragma unroll 1
    for (int kc = 0; kc < NKC; kc++) {
        if (kc + 1 < NKC)
            asm volatile("cp.async.wait_group 1;" ::: "memory");
        else
            asm volatile("cp.async.wait_group 0;" ::: "memory");
        __syncthreads();
        if (kc + 2 < NKC) issue((kc + 2) % 3, kc + 2);
        const uint32_t bo = sbase + (uint32_t)((kc % 3) * M128_STG) * 2;
#pragma unroll
        for (int ks = 0; ks < 4; ks++) {
            const uint32_t sub = bo + (uint32_t)((ks >> 1) * 2 * M128_REG) * 2;
            const int k0 = (ks & 1) * 16;
            uint32_t bh[4][2];
#pragma unroll
            for (int p = 0; p < 2; p++) {
                uint32_t ab = sub +
                    (uint32_t)(M128_REG + (wn * 32 + p * 16 + brow) * LDT + k0 + bkof) * 2;
                ldsm4(bh[2 * p][0], bh[2 * p][1], bh[2 * p + 1][0], bh[2 * p + 1][1], ab);
            }
#pragma unroll
            for (int mf = 0; mf < 2; mf++) {
                uint32_t ah[4];
                uint32_t aa = sub + (uint32_t)((wm * 32 + mf * 16 + arow) * LDT + k0 + akof) * 2;
                ldsm4(ah[0], ah[1], ah[2], ah[3], aa);
#pragma unroll
                for (int nf = 0; nf < 4; nf++) mma16816(acc[mf][nf], ah, bh[nf]);
            }
        }
    }
    __syncthreads();

#pragma unroll
    for (int mf = 0; mf < 2; mf++) {
#pragma unroll
        for (int half = 0; half < 2; half++) {
            int mg = bm0 + wm * 32 + mf * 16 + (lane >> 2) + half * 8;
#pragma unroll
            for (int nf = 0; nf < 4; nf++) {
                int n = bn0 + wn * 32 + nf * 8 + (lane & 3) * 2;
                float2 v{acc[mf][nf][half * 2 + 0], acc[mf][nf][half * 2 + 1]};
                *reinterpret_cast<float2*>(C + (size_t)mg * ldc + n) = v;
            }
        }
    }
}

// ---------------- logits tile 128x256, 512 thr, 3-stage (device fn) ----------------
__device__ void logits_tile(char* smem, int tt, int nt,
                            const float* __restrict__ bias, float* __restrict__ C) {
    const int tid = threadIdx.x, lane = tid & 31, wid = tid >> 5;
    const int wm = wid & 3, wn = wid >> 2;
    const int bm0 = tt * 128, bn0 = nt * 256;
    const uint32_t sbase = smem_u32(smem);
    const __half* Ah = g_Hallhi;
    const __half* Bh = g_owThi;

    float acc[2][8][4];
#pragma unroll
    for (int i = 0; i < 2; i++)
#pragma unroll
        for (int j = 0; j < 8; j++)
#pragma unroll
            for (int k = 0; k < 4; k++) acc[i][j][k] = 0.f;

    auto issue = [&](int st, int kc) {
        const int k0 = kc * 32;
        {
            int r = tid >> 2, sg = tid & 3;
            uint32_t so = sbase + (uint32_t)(st * BIG_STG + r * LDT + sg * 8) * 2;
            cp16(so, Ah + (size_t)(bm0 + r) * Hv + k0 + sg * 8);
        }
#pragma unroll
        for (int j = 0; j < 2; j++) {
            int c = tid + j * 512;
            int r = c >> 2, sg = c & 3;
            uint32_t so = sbase + (uint32_t)(st * BIG_STG + BIG_OFFB + r * LDT + sg * 8) * 2;
            cp16(so, Bh + (size_t)(bn0 + r) * Hv + k0 + sg * 8);
        }
        asm volatile("cp.async.commit_group;" ::: "memory");
    };

    const int arow = ((lane >> 3) & 1) * 8 + (lane & 7);
    const int akof = (lane >> 4) * 8;
    const int brow = ((lane >> 4) & 1) * 8 + (lane & 7);
    const int bkof = ((lane >> 3) & 1) * 8;

    constexpr int NKC = Hv / 32;
    issue(0, 0);
    issue(1, 1);
    for (int kc = 0; kc < NKC; kc++) {
        if (kc + 1 < NKC)
            asm volatile("cp.async.wait_group 1;" ::: "memory");
        else
            asm volatile("cp.async.wait_group 0;" ::: "memory");
        __syncthreads();
        if (kc + 2 < NKC) issue((kc + 2) % 3, kc + 2);
        const uint32_t bo = sbase + (uint32_t)((kc % 3) * BIG_STG) * 2;
#pragma unroll
        for (int ks = 0; ks < 2; ks++) {
            const int k0 = ks * 16;
            uint32_t bf[8][2];
#pragma unroll
            for (int p = 0; p < 4; p++) {
                uint32_t ab = bo +
                    (uint32_t)(BIG_OFFB + (wn * 64 + p * 16 + brow) * LDT + k0 + bkof) * 2;
                ldsm4(bf[2 * p][0], bf[2 * p][1], bf[2 * p + 1][0], bf[2 * p + 1][1], ab);
            }
#pragma unroll
            for (int mf = 0; mf < 2; mf++) {
                uint32_t ah4[4];
                uint32_t aa = bo + (uint32_t)((wm * 32 + mf * 16 + arow) * LDT + k0 + akof) * 2;
                ldsm4(ah4[0], ah4[1], ah4[2], ah4[3], aa);
#pragma unroll
                for (int nf = 0; nf < 8; nf++) mma16816(acc[mf][nf], ah4, bf[nf]);
            }
        }
    }
    __syncthreads();

#pragma unroll
    for (int mf = 0; mf < 2; mf++) {
#pragma unroll
        for (int half = 0; half < 2; half++) {
            int bb = wm * 32 + mf * 16 + (lane >> 2) + half * 8;
            float* dst = C + ((size_t)bb * Tv + tt) * (size_t)Vv;
#pragma unroll
            for (int nf = 0; nf < 8; nf++) {
                int n = bn0 + wn * 64 + nf * 8 + (lane & 3) * 2;
                float2 v;
                v.x = acc[mf][nf][half * 2 + 0] + bias[n];
                v.y = acc[mf][nf][half * 2 + 1] + bias[n + 1];
                *reinterpret_cast<float2*>(dst + n) = v;
            }
        }
    }
}

// ---------------- FUSED persistent kernel (512 threads) ----------------
__global__ void __launch_bounds__(THR) loop_fused(
    const float* __restrict__ fc1_b,
    const float* __restrict__ score_w, const float* __restrict__ score_b,
    const float* __restrict__ sm_w, const float* __restrict__ lm_w,
    const float* __restrict__ sm_b, const float* __restrict__ lm_b,
    float* __restrict__ wout, const float* __restrict__ out_b,
    float* __restrict__ outp) {
    extern __shared__ char smem[];
    __shared__ unsigned sh_idx;
    const int tid = threadIdx.x, lane = tid & 31, warp = tid >> 5;
    const int blk = blockIdx.x;
    unsigned tgt = 0;

    if (blk < NBLK) {
        // -------- pre-phase: h0/c0 split-K tiles (2 per block) --------
        {
#pragma unroll
            for (int q = 0; q < SK_TILES / NBLK; q++) {
                int r = blk * (SK_TILES / NBLK) + q;
                int mat = r >> 7, rem = r & 127;
                sk_tile(smem, mat ? lm_w : sm_w, mat ? g_cp : g_hp,
                        rem >> 5, (rem & 31) * 32);
                __syncthreads();
            }
        }
        gridbar(tgt);

        // -------- prologue: reduce h0/c0 for batch b = blk --------
        {
            const int b = blk;
            for (int j = tid; j < Hv; j += THR) {
                int idx = b * Hv + j;
                float h = sm_b[j], c = lm_b[j];
#pragma unroll
                for (int s = 0; s < S_HC; s++) {
                    h += g_hp[(size_t)s * Bv * Hv + idx];
                    c += g_cp[(size_t)s * Bv * Hv + idx];
                }
                g_c[idx] = c;
                g_cathi[(size_t)b * CAT + Fv + j] = __float2half_rn(h);
            }
        }
        gridbar(tgt);

        for (int t = 0; t < Tv; t++) {
            // ---------- P1: xd partials = h(fp16) @ fc1T (mma, 32 blocks) ----------
            if (blk < 32) {
                const int nt = blk & 3, ksp = blk >> 2;
                const int kbeg = ksp * (Hv / S_XD);
                float* P = g_xdp + (size_t)ksp * Bv * Av;
                mma128_tile(smem, g_cathi + Fv + kbeg, CAT,
                            g_fc1Thi + kbeg, Hv, Hv / S_XD, P, Av, 0, nt * 128);
            }
            gridbar(tgt);

            // ---------- P2: attention + softmax + context (block = batch b) ----------
            {
                float* xd_s = (float*)smem;      // 512
                float* sc = xd_s + Av;           // 64
                float* al = sc + Lv;             // 64
                float* red = al + Lv;            // 2
                const int b = blk;
                {
                    int a = tid;  // THR == Av
                    float s = fc1_b[a];
#pragma unroll
                    for (int p = 0; p < S_XD; p++) s += g_xdp[(size_t)p * Bv * Av + b * Av + a];
                    xd_s[a] = s;
                }
                __syncthreads();
                for (int l = warp; l < Lv; l += 16) {
                    const __half2* xe2 =
                        reinterpret_cast<const __half2*>(g_xench + (size_t)(b * Lv + l) * Av);
                    float s = 0.f;
                    for (int a = lane; a < Av / 2; a += 32) {
                        float2 x = __half22float2(xe2[a]);
                        s += tanh_fast(x.x + xd_s[2 * a]) * score_w[2 * a];
                        s += tanh_fast(x.y + xd_s[2 * a + 1]) * score_w[2 * a + 1];
                    }
#pragma unroll
                    for (int o = 16; o; o >>= 1) s += __shfl_xor_sync(0xFFFFFFFFu, s, o);
                    if (lane == 0) sc[l] = s + score_b[0];
                }
                __syncthreads();
                if (warp == 0) {
                    float m = fmaxf(sc[lane], sc[lane + 32]);
#pragma unroll
                    for (int o = 16; o; o >>= 1)
                        m = fmaxf(m, __shfl_xor_sync(0xFFFFFFFFu, m, o));
                    float s = expf(sc[lane] - m) + expf(sc[lane + 32] - m);
#pragma unroll
                    for (int o = 16; o; o >>= 1) s += __shfl_xor_sync(0xFFFFFFFFu, s, o);
                    if (lane == 0) { red[0] = m; red[1] = s; }
                }
                __syncthreads();
                float inv = 1.0f / red[1], smax = red[0];
                if (tid < Lv) {
                    float a = expf(sc[tid] - smax) * inv;
                    al[tid] = a;
                    if (wout) wout[((size_t)b * Tv + t) * Lv + tid] = a;
                }
                __syncthreads();
                const __half2* Xb2 =
                    reinterpret_cast<const __half2*>(g_Xhi + (size_t)b * Lv * Fv);
                __half2* cat2 = reinterpret_cast<__half2*>(g_cathi + (size_t)b * CAT);
                for (int f2 = tid; f2 < Fv / 2; f2 += THR) {
                    float sx = 0.f, sy = 0.f;
#pragma unroll
                    for (int l = 0; l < Lv; l++) {
                        float2 x = __half22float2(Xb2[(size_t)l * (Fv / 2) + f2]);
                        sx = fmaf(al[l], x.x, sx);
                        sy = fmaf(al[l], x.y, sy);
                    }
                    cat2[f2] = __floats2half2_rn(sx, sy);
                }
            }
            gridbar(tgt);

            // ---------- P3: gates partials = cat @ WcatT (1-pass fp16 mma, split-K) ----------
            {
                constexpr int KSPAN = CAT / S_GT;     // 768
                const int bn0 = (blk & 31) * 128;
                const int ksp = blk >> 5;
                const int kbeg = ksp * KSPAN;
                float* P = g_gatep + (size_t)ksp * Bv * G4H;
                mma128_tile(smem, g_cathi + kbeg, CAT, g_WcatThi + kbeg, CAT,
                            KSPAN, P, G4H, 0, bn0);
            }
            gridbar(tgt);

            // ---------- P4: gates reduce + LSTM pointwise (b = blk) ----------
            {
                const int b = blk;
                for (int j = tid; j < Hv; j += THR) {
                    int idx = b * Hv + j;
                    size_t base = (size_t)b * G4H;
                    const float* EG = g_embgate + ((size_t)t * Bv) * G4H + base;
                    float ig = EG[j], fg = EG[Hv + j], gg = EG[2 * Hv + j], og = EG[3 * Hv + j];
#pragma unroll
                    for (int s = 0; s < S_GT; s++) {
                        const float* P = g_gatep + (size_t)s * Bv * G4H + base;
                        ig += P[j];
                        fg += P[Hv + j];
                        gg += P[2 * Hv + j];
                        og += P[3 * Hv + j];
                    }
                    ig = sigmoidf_(ig);
                    fg = sigmoidf_(fg);
                    og = sigmoidf_(og);
                    gg = tanhf(gg);
                    float c2 = fg * g_c[idx] + ig * gg;
                    float h2 = og * tanhf(c2);
                    g_c[idx] = c2;
                    __half hh = __float2half_rn(h2);
                    g_cathi[(size_t)b * CAT + Fv + j] = hh;
                    g_Hallhi[((size_t)t * Bv + b) * Hv + j] = hh;
                }
            }
            gridbar(tgt);
            if (blk == 0 && tid == 0)
                asm volatile("st.release.gpu.u32 [%0], %1;"
                             :: "l"(&g_tdone), "r"((unsigned)(t + 1)) : "memory");
        }
    }

    // =================== logits tiles (128x256): work-stealing, all blocks ===================
    for (;;) {
        __syncthreads();
        if (tid == 0) sh_idx = atomicAdd(&g_tile, 1u);
        __syncthreads();
        unsigned idx = sh_idx;
        if (idx >= (unsigned)NTILES) break;
        int tt = (int)(idx / NT_N), nt = (int)(idx % NT_N);
        if (tid == 0) {
            unsigned v;
            do {
                asm volatile("ld.acquire.gpu.u32 %0, [%1];" : "=r"(v)
                             : "l"(&g_tdone) : "memory");
                if ((int)v > tt) break;
                __nanosleep(64);
            } while (true);
        }
        __syncthreads();
        logits_tile(smem, tt, nt, out_b, outp);
    }
}

// ---------------- merged preproc GEMM (x_enc + embgate), 256 thr, 2-stage ----------------
__global__ void __launch_bounds__(256) gemm_pre(
    const float* __restrict__ fc2_b,
    const float* __restrict__ b_ih, const float* __restrict__ b_hh) {
    constexpr int RBUF = 2 * 128 * LDT;
    constexpr int OFF_B = 128 * LDT;
    extern __shared__ __half smb[];
    const int tid = threadIdx.x, lane = tid & 31, wid = tid >> 5;
    const int wm = wid & 1, wn = wid >> 1;
    const uint32_t sbase = smem_u32(smb);

    const __half *Ah, *Bh;
    int lda, ldb, Kspan, bm0, bn0, ldc;
    const float *b1, *b2;
    bool hout;
    __half* Ch = nullptr;
    float* Cf = nullptr;
    if ((int)blockIdx.x < PRE_XENC) {
        int r = blockIdx.x;
        bm0 = (r >> 2) * 128;
        bn0 = (r & 3) * 128;
        Ah = g_Xhi; lda = Fv; Bh = g_fc2Thi; ldb = Fv; Kspan = Fv;
        Ch = g_xench; ldc = Av; b1 = fc2_b; b2 = nullptr; hout = true;
    } else {
        int r = blockIdx.x - PRE_XENC;
        bm0 = (r >> 5) * 128;
        bn0 = (r & 31) * 128;
        Ah = g_embxhi; lda = Ev; Bh = g_wihEThi; ldb = Ev; Kspan = Ev;
        Cf = g_embgate; ldc = G4H; b1 = b_ih; b2 = b_hh; hout = false;
    }

    float acc[4][4][4];
#pragma unroll
    for (int i = 0; i < 4; i++)
#pragma unroll
        for (int j = 0; j < 4; j++)
#pragma unroll
            for (int k = 0; k < 4; k++) acc[i][j][k] = 0.f;

    auto issue = [&](int buf, int kc) {
        const int k0 = kc * 32;
#pragma unroll
        for (int j = 0; j < 2; j++) {
            int c = tid + j * 256;
            int r = c >> 2, sg = c & 3;
            uint32_t so = sbase + (uint32_t)(buf * RBUF + r * LDT + sg * 8) * 2;
            cp16(so, Ah + (size_t)(bm0 + r) * lda + k0 + sg * 8);
            cp16(so + OFF_B * 2, Bh + (size_t)(bn0 + r) * ldb + k0 + sg * 8);
        }
        asm volatile("cp.async.commit_group;" ::: "memory");
    };

    const int arow = ((lane >> 3) & 1) * 8 + (lane & 7);
    const int akof = (lane >> 4) * 8;
    const int brow = ((lane >> 4) & 1) * 8 + (lane & 7);
    const int bkof = ((lane >> 3) & 1) * 8;

    const int NKC = Kspan / 32;
    issue(0, 0);
    for (int kc = 0; kc < NKC; kc++) {
        if (kc + 1 < NKC) {
            issue((kc + 1) & 1, kc + 1);
            asm volatile("cp.async.wait_group 1;" ::: "memory");
        } else {
            asm volatile("cp.async.wait_group 0;" ::: "memory");
        }
        __syncthreads();
        const uint32_t bo = sbase + (uint32_t)((kc & 1) * RBUF) * 2;
#pragma unroll
        for (int ks = 0; ks < 2; ks++) {
            const int k0 = ks * 16;
            uint32_t bh[4][2];
#pragma unroll
            for (int p = 0; p < 2; p++) {
                uint32_t ab = bo + (uint32_t)(OFF_B + (wn * 32 + p * 16 + brow) * LDT + k0 + bkof) * 2;
                ldsm4(bh[2 * p][0], bh[2 * p][1], bh[2 * p + 1][0], bh[2 * p + 1][1], ab);
            }
#pragma unroll
            for (int mf = 0; mf < 4; mf++) {
                uint32_t ah[4];
                uint32_t aa = bo + (uint32_t)((wm * 64 + mf * 16 + arow) * LDT + k0 + akof) * 2;
                ldsm4(ah[0], ah[1], ah[2], ah[3], aa);
#pragma unroll
                for (int nf = 0; nf < 4; nf++) mma16816(acc[mf][nf], ah, bh[nf]);
            }
        }
        __syncthreads();
    }

#pragma unroll
    for (int mf = 0; mf < 4; mf++) {
#pragma unroll
        for (int half = 0; half < 2; half++) {
            int m = bm0 + wm * 64 + mf * 16 + (lane >> 2) + half * 8;
#pragma unroll
            for (int nf = 0; nf < 4; nf++) {
                int n = bn0 + wn * 32 + nf * 8 + (lane & 3) * 2;
                float vx = acc[mf][nf][half * 2 + 0] + b1[n];
                float vy = acc[mf][nf][half * 2 + 1] + b1[n + 1];
                if (b2) { vx += b2[n]; vy += b2[n + 1]; }
                if (hout) {
                    *reinterpret_cast<__half2*>(Ch + (size_t)m * ldc + n) =
                        __floats2half2_rn(vx, vy);
                } else {
                    float2 v{vx, vy};
                    *reinterpret_cast<float2*>(Cf + (size_t)m * ldc + n) = v;
                }
            }
        }
    }
}

// ---------------- host orchestration ----------------
extern "C" void kernel_launch(void* const* d_in, const int* in_sizes, int n_in,
                              void* d_out, int out_size) {
    const float* X       = (const float*)d_in[0];
    const void*  yraw    = d_in[1];
    const float* emb     = (const float*)d_in[2];
    const float* fc1_w   = (const float*)d_in[3];
    const float* fc1_b   = (const float*)d_in[4];
    const float* fc2_w   = (const float*)d_in[5];
    const float* fc2_b   = (const float*)d_in[6];
    const float* score_w = (const float*)d_in[7];
    const float* score_b = (const float*)d_in[8];
    const float* sm_w    = (const float*)d_in[9];
    const float* sm_b    = (const float*)d_in[10];
    const float* lm_w    = (const float*)d_in[11];
    const float* lm_b    = (const float*)d_in[12];
    const float* w_ih    = (const float*)d_in[13];
    const float* b_ih    = (const float*)d_in[14];
    const float* w_hh    = (const float*)d_in[15];
    const float* b_hh    = (const float*)d_in[16];
    const float* out_w   = (const float*)d_in[17];
    const float* out_b   = (const float*)d_in[18];

    float* outp = (float*)d_out;
    const size_t osz = (size_t)Bv * Tv * Vv;
    const size_t wsz = (size_t)Bv * Tv * Lv;
    float* wout = ((size_t)out_size >= osz + wsz) ? (outp + osz) : nullptr;

    static int smem_set = 0;
    if (!smem_set) {
        cudaFuncSetAttribute(loop_fused, cudaFuncAttributeMaxDynamicSharedMemorySize,
                             SMEM_FUSED);
        cudaFuncSetAttribute(gemm_pre, cudaFuncAttributeMaxDynamicSharedMemorySize,
                             SMEM_P1);
        smem_set = 1;
    }

    // --- launch 1: all elementwise prep + all weight transposes (vectorized) ---
    {
        constexpr int NCVX = (Bv * Lv * Fv) / 4 / 256;
        constexpr int NMEAN = (Bv * Fv) / 256;
        constexpr int NGATH = (Tv * Bv * Ev) / 256;
        constexpr int NTW = (Hv / 32) * (Vv / 128) + (CAT / 32) * (G4H / 128) +
                            (Fv / 32) * (Av / 128) + (Ev / 32) * (G4H / 128) +
                            (Hv / 32) * (Av / 128);
        prep_all<<<NCVX + NMEAN + NGATH + NTW, 256>>>(
            X, yraw, emb, out_w, w_ih, w_hh, fc2_w, fc1_w);
    }
    // --- launch 2: merged preproc GEMMs (x_enc + embgate; 2 blocks/SM) ---
    gemm_pre<<<PRE_XENC + PRE_EMBG, 256, SMEM_P1>>>(fc2_b, b_ih, b_hh);

    // --- launch 3: h0/c0 split-K + persistent loop + overlapped logits ---
    loop_fused<<<NFUSE, THR, SMEM_FUSED>>>(
        fc1_b, score_w, score_b, sm_w, lm_w, sm_b, lm_b,
        wout, out_b, outp);
}

// round 17
// speedup vs baseline: 1.4435x; 1.4435x over previous
#include <cuda_runtime.h>
#include <cuda_fp16.h>
#include <cstdint>

// ---------------- problem constants ----------------
namespace {
constexpr int Bv = 128, Lv = 64, Tv = 20, Vv = 32000;
constexpr int Ev = 512, Hv = 1024, Av = 512, Fv = 2048;
constexpr int G4H = 4 * Hv;          // 4096
constexpr int CAT = Fv + Hv;         // 3072 : [ctx | h]
constexpr int S_XD = 8, S_GT = 4, S_HC = 4;
constexpr int LDT = 40;              // smem leading dim (fp16), conflict-free pad
constexpr int NBLK = 128;            // loop blocks
constexpr int NFUSE = 148;           // fused grid
constexpr int THR = 512;             // threads per fused block
constexpr int NT_N = Vv / 256;       // 125 logits n-tiles (256 wide)
constexpr int NTILES = Tv * NT_N;    // 2500 logits tiles
constexpr int SK_TILES = 2 * S_HC * (Hv / 32);  // 256 h0/c0 split-K tiles
// preproc merged GEMM
constexpr int PRE_XENC = (Bv * Lv / 128) * (Av / 128);   // 256
constexpr int PRE_EMBG = (Tv * Bv / 128) * (G4H / 128);  // 640
// big logits tile: 128x256, 3-stage
constexpr int BIG_STG = (128 + 256) * LDT;
constexpr int BIG_OFFB = 128 * LDT;
constexpr int SMEM_BIG = 3 * BIG_STG * 2;         // 92160 bytes
constexpr int SMEM_P1 = 2 * (2 * 128 * LDT) * 2;  // 40960 (preproc gemms)
constexpr int SMEM_FUSED = SMEM_BIG;
}

// ---------------- scratch (device globals) ----------------
__device__ float g_mean[Bv * Fv];
__device__ float g_c[Bv * Hv];
__device__ float g_embgate[(size_t)Tv * Bv * G4H];
__device__ float g_xdp[(size_t)S_XD * Bv * Av];
__device__ float g_gatep[(size_t)S_GT * Bv * G4H];
__device__ float g_hp[(size_t)S_HC * Bv * Hv];
__device__ float g_cp[(size_t)S_HC * Bv * Hv];
__device__ unsigned g_bar;
__device__ unsigned g_tile;
__device__ unsigned g_tdone;
// fp16 operands
__device__ __half g_Xhi[(size_t)Bv * Lv * Fv];
__device__ __half g_xench[(size_t)Bv * Lv * Av];
__device__ __half g_embxhi[(size_t)Tv * Bv * Ev];
__device__ __half g_cathi[(size_t)Bv * CAT];
__device__ __half g_Hallhi[(size_t)Tv * Bv * Hv];
__device__ __half g_owThi[(size_t)Vv * Hv];
__device__ __half g_WcatThi[(size_t)G4H * CAT];
__device__ __half g_fc2Thi[(size_t)Av * Fv];
__device__ __half g_wihEThi[(size_t)G4H * Ev];
__device__ __half g_fc1Thi[(size_t)Av * Hv];

__device__ __forceinline__ float sigmoidf_(float x) { return 1.0f / (1.0f + expf(-x)); }

__device__ __forceinline__ float rcp_fast(float d) {
    float r = __int_as_float(0x7EF311C3 - __float_as_int(d));
    r = r * (2.0f - d * r);
    r = r * (2.0f - d * r);
    return r;
}
__device__ __forceinline__ float tanh_fast(float x) {
    x = fminf(fmaxf(x, -4.97f), 4.97f);
    float x2 = x * x;
    float num = x * (135135.f + x2 * (17325.f + x2 * (378.f + x2)));
    float den = 135135.f + x2 * (62370.f + x2 * (3150.f + x2 * 28.f));
    return num * rcp_fast(den);
}

// ---------------- PTX helpers ----------------
__device__ __forceinline__ uint32_t smem_u32(const void* p) {
    uint32_t a;
    asm("{ .reg .u64 t; cvta.to.shared.u64 t, %1; cvt.u32.u64 %0, t; }" : "=r"(a) : "l"(p));
    return a;
}
__device__ __forceinline__ void cp16(uint32_t s, const void* g) {
    asm volatile("cp.async.cg.shared.global [%0], [%1], 16;" :: "r"(s), "l"(g));
}
__device__ __forceinline__ void ldsm4(uint32_t& r0, uint32_t& r1, uint32_t& r2,
                                      uint32_t& r3, uint32_t a) {
    asm volatile("ldmatrix.sync.aligned.m8n8.x4.shared.b16 {%0,%1,%2,%3}, [%4];"
                 : "=r"(r0), "=r"(r1), "=r"(r2), "=r"(r3) : "r"(a));
}
__device__ __forceinline__ void mma16816(float* c, const uint32_t* a, const uint32_t* b) {
    asm volatile(
        "mma.sync.aligned.m16n8k16.row.col.f32.f16.f16.f32 "
        "{%0,%1,%2,%3}, {%4,%5,%6,%7}, {%8,%9}, {%0,%1,%2,%3};"
        : "+f"(c[0]), "+f"(c[1]), "+f"(c[2]), "+f"(c[3])
        : "r"(a[0]), "r"(a[1]), "r"(a[2]), "r"(a[3]), "r"(b[0]), "r"(b[1]));
}

// grid barrier among the NBLK loop blocks (round-13 proven form)
__device__ __forceinline__ void gridbar(unsigned& tgt) {
    __syncthreads();
    if (threadIdx.x == 0) {
        tgt += NBLK;
        __threadfence();
        atomicAdd(&g_bar, 1u);
        unsigned v;
        do {
            asm volatile("ld.acquire.gpu.u32 %0, [%1];" : "=r"(v) : "l"(&g_bar) : "memory");
            if (v >= tgt) break;
            __nanosleep(32);
        } while (true);
    }
    __syncthreads();
}

// ---------------- prep_all: counters + convX + mean + gather + ALL transposes ----------------
// transpose tiles are 32(k) x 128(n), float4 loads, 2x16B transposed stores.
__global__ void prep_all(const float* __restrict__ X, const void* __restrict__ yraw,
                         const float* __restrict__ emb,
                         const float* __restrict__ out_w,
                         const float* __restrict__ w_ih,
                         const float* __restrict__ w_hh,
                         const float* __restrict__ fc2_w,
                         const float* __restrict__ fc1_w) {
    constexpr int NCVX = (Bv * Lv * Fv) / 4 / 256;   // 16384
    constexpr int NMEAN = (Bv * Fv) / 256;           // 1024
    constexpr int NGATH = (Tv * Bv * Ev) / 256;      // 2560
    constexpr int B0 = NCVX, B1 = B0 + NMEAN, B2 = B1 + NGATH;
    constexpr int TOW = (Hv / 32) * (Vv / 128);      // 8000
    constexpr int TWC = (CAT / 32) * (G4H / 128);    // 3072
    constexpr int TF2 = (Fv / 32) * (Av / 128);      // 256
    constexpr int TWE = (Ev / 32) * (G4H / 128);     // 512
    constexpr int B3 = B2 + TOW, B4 = B3 + TWC, B5 = B4 + TF2, B6 = B5 + TWE;
    const int bid = blockIdx.x;
    const int tid = threadIdx.x;
    if (bid == 0 && tid == 0) { g_bar = 0; g_tile = 0; g_tdone = 0; }
    if (bid < B0) {
        size_t i = (size_t)bid * 256 + tid;
        float4 v = ((const float4*)X)[i];
        __half2* o = reinterpret_cast<__half2*>(g_Xhi) + 2 * i;
        o[0] = __floats2half2_rn(v.x, v.y);
        o[1] = __floats2half2_rn(v.z, v.w);
        return;
    }
    if (bid < B1) {
        int idx = (bid - B0) * 256 + tid;
        int f = idx % Fv, b = idx / Fv;
        const float* Xb = X + (size_t)b * Lv * Fv + f;
        float s = 0.f;
#pragma unroll
        for (int l = 0; l < Lv; l++) s += Xb[(size_t)l * Fv];
        g_mean[idx] = s * (1.0f / Lv);
        return;
    }
    if (bid < B2) {
        __shared__ int ok;
        if (tid == 0) ok = 1;
        __syncthreads();
        const int* y32 = (const int*)yraw;
        for (int i = tid; i < (Bv * (Tv + 1)) / 2; i += 256)
            if (y32[2 * i + 1] != 0) ok = 0;
        __syncthreads();
        size_t idx = (size_t)(bid - B1) * 256 + tid;
        int e = (int)(idx % Ev);
        int r = (int)(idx / Ev);
        int b = r % Bv, t = r / Bv;
        int token;
        if (ok)
            token = (int)((const long long*)yraw)[(size_t)b * (Tv + 1) + t];
        else
            token = y32[(size_t)b * (Tv + 1) + t];
        g_embxhi[idx] = __float2half_rn(emb[(size_t)token * Ev + e]);
        return;
    }
    // ---- transposes: 32(k) x 128(n) tiles ----
    __shared__ float tile[32][129];
    const float *s1, *s2;
    int Ksplit, K, N;
    __half* dhi;
    int r, nc;
    if (bid < B3) {                          // out_w -> owThi [Vv, Hv]
        r = bid - B2;
        s1 = out_w; s2 = nullptr; Ksplit = Hv; K = Hv; N = Vv; dhi = g_owThi;
        nc = Vv / 128;
    } else if (bid < B4) {                   // [w_ih[E:]; w_hh] -> WcatThi [G4H, CAT]
        r = bid - B3;
        s1 = w_ih + (size_t)Ev * G4H; s2 = w_hh; Ksplit = Fv; K = CAT; N = G4H;
        dhi = g_WcatThi;
        nc = G4H / 128;
    } else if (bid < B5) {                   // fc2_w -> fc2Thi [Av, Fv]
        r = bid - B4;
        s1 = fc2_w; s2 = nullptr; Ksplit = Fv; K = Fv; N = Av; dhi = g_fc2Thi;
        nc = Av / 128;
    } else if (bid < B6) {                   // w_ih[:E] -> wihEThi [G4H, Ev]
        r = bid - B5;
        s1 = w_ih; s2 = nullptr; Ksplit = Ev; K = Ev; N = G4H; dhi = g_wihEThi;
        nc = G4H / 128;
    } else {                                 // fc1_w -> fc1Thi [Av, Hv]
        r = bid - B6;
        s1 = fc1_w; s2 = nullptr; Ksplit = Hv; K = Hv; N = Av; dhi = g_fc1Thi;
        nc = Av / 128;
    }
    const int n0 = (r % nc) * 128, k0 = (r / nc) * 32;
#pragma unroll
    for (int it = 0; it < 4; it++) {
        int i = tid + it * 256;
        int kr = i >> 5, c4 = i & 31;
        int k = k0 + kr;
        const float* s = (k < Ksplit) ? (s1 + (size_t)k * N)
                                      : (s2 + (size_t)(k - Ksplit) * N);
        float4 v = *reinterpret_cast<const float4*>(s + n0 + c4 * 4);
        tile[kr][c4 * 4 + 0] = v.x;
        tile[kr][c4 * 4 + 1] = v.y;
        tile[kr][c4 * 4 + 2] = v.z;
        tile[kr][c4 * 4 + 3] = v.w;
    }
    __syncthreads();
    {
        int n = tid >> 1, part = (tid & 1) * 16;
        __half h[16];
#pragma unroll
        for (int j = 0; j < 16; j++) h[j] = __float2half_rn(tile[part + j][n]);
        __half* dst = dhi + (size_t)(n0 + n) * K + k0 + part;
        *reinterpret_cast<uint4*>(dst) = *reinterpret_cast<uint4*>(h);
        *reinterpret_cast<uint4*>(dst + 8) = *reinterpret_cast<uint4*>(h + 8);
    }
}

// ---------------- SIMT split-K tile for h0/c0 (512 threads, device fn) ----------------
__device__ void sk_tile(char* smem, const float* __restrict__ Bw,
                        float* __restrict__ Part, int s, int bn0) {
    float* As = (float*)smem;           // [32][132]
    float* Bs = As + 32 * 132;          // [32][32]
    const int tid = threadIdx.x;
    const int tx = tid & 15, ty = tid >> 4;
    const int Ks = Fv / S_HC;
    const int kbeg = s * Ks;
    float acc[4][2] = {};
    for (int k0 = kbeg; k0 < kbeg + Ks; k0 += 32) {
#pragma unroll
        for (int it = 0; it < 8; it++) {
            int i = tid + it * THR;
            int r = i >> 5, c = i & 31;
            As[c * 132 + r] = g_mean[(size_t)r * Fv + k0 + c];
        }
#pragma unroll
        for (int it = 0; it < 2; it++) {
            int i = tid + it * THR;
            int r = i >> 5, c = i & 31;
            Bs[r * 32 + c] = Bw[(size_t)(k0 + r) * Hv + bn0 + c];
        }
        __syncthreads();
#pragma unroll
        for (int kk = 0; kk < 32; kk++) {
            float ar[4];
            float br0 = Bs[kk * 32 + tx * 2], br1 = Bs[kk * 32 + tx * 2 + 1];
            *reinterpret_cast<float4*>(ar) =
                *reinterpret_cast<const float4*>(&As[kk * 132 + ty * 4]);
#pragma unroll
            for (int i = 0; i < 4; i++) {
                acc[i][0] = fmaf(ar[i], br0, acc[i][0]);
                acc[i][1] = fmaf(ar[i], br1, acc[i][1]);
            }
        }
        __syncthreads();
    }
    float* P = Part + (size_t)s * 128 * Hv;
#pragma unroll
    for (int i = 0; i < 4; i++) {
        int r = ty * 4 + i;
        P[(size_t)r * Hv + bn0 + tx * 2] = acc[i][0];
        P[(size_t)r * Hv + bn0 + tx * 2 + 1] = acc[i][1];
    }
}

// ---------------- 128x128 1-pass fp16 mma tile, 512 threads, 3-stage, K32 (round-13) ----------------
__device__ void mma128_tile(char* smem,
                            const __half* __restrict__ A, int lda,
                            const __half* __restrict__ B, int ldb, int K,
                            float* __restrict__ C, int ldc,
                            int bm0, int bn0) {
    constexpr int STG = 2 * 128 * LDT;   // halfs per stage (A+B)
    constexpr int OFF_B = 128 * LDT;
    const int tid = threadIdx.x, lane = tid & 31, warp = tid >> 5;
    const int wm = warp & 3, wn = warp >> 2;  // 4(M) x 4(N) warps, each 32x32
    const uint32_t sbase = smem_u32(smem);
    float acc[2][4][4] = {};
    const int arow = ((lane >> 3) & 1) * 8 + (lane & 7);
    const int akof = (lane >> 4) * 8;
    const int brow = ((lane >> 4) & 1) * 8 + (lane & 7);
    const int bkof = ((lane >> 3) & 1) * 8;
    const int NKC = K / 32;

    auto issue = [&](int st, int kc) {
        const int k0 = kc * 32;
        int r = tid >> 2, sg = tid & 3;
        uint32_t so = sbase + (uint32_t)(st * STG + r * LDT + sg * 8) * 2;
        cp16(so, A + (size_t)(bm0 + r) * lda + k0 + sg * 8);
        cp16(so + OFF_B * 2, B + (size_t)(bn0 + r) * ldb + k0 + sg * 8);
        asm volatile("cp.async.commit_group;" ::: "memory");
    };

    issue(0, 0);
    if (NKC > 1) issue(1, 1);
#pragma unroll 1
    for (int kc = 0; kc < NKC; kc++) {
        if (kc + 1 < NKC)
            asm volatile("cp.async.wait_group 1;" ::: "memory");
        else
            asm volatile("cp.async.wait_group 0;" ::: "memory");
        __syncthreads();
        if (kc + 2 < NKC) issue((kc + 2) % 3, kc + 2);
        const uint32_t bo = sbase + (uint32_t)((kc % 3) * STG) * 2;
#pragma unroll
        for (int ks = 0; ks < 2; ks++) {
            const int k0 = ks * 16;
            uint32_t bh[4][2];
#pragma unroll
            for (int p = 0; p < 2; p++) {
                uint32_t ab = bo +
                    (uint32_t)(OFF_B + (wn * 32 + p * 16 + brow) * LDT + k0 + bkof) * 2;
                ldsm4(bh[2 * p][0], bh[2 * p][1], bh[2 * p + 1][0], bh[2 * p + 1][1], ab);
            }
#pragma unroll
            for (int mf = 0; mf < 2; mf++) {
                uint32_t ah[4];
                uint32_t aa = bo + (uint32_t)((wm * 32 + mf * 16 + arow) * LDT + k0 + akof) * 2;
                ldsm4(ah[0], ah[1], ah[2], ah[3], aa);
#pragma unroll
                for (int nf = 0; nf < 4; nf++) mma16816(acc[mf][nf], ah, bh[nf]);
            }
        }
    }
    __syncthreads();

#pragma unroll
    for (int mf = 0; mf < 2; mf++) {
#pragma unroll
        for (int half = 0; half < 2; half++) {
            int mg = bm0 + wm * 32 + mf * 16 + (lane >> 2) + half * 8;
#pragma unroll
            for (int nf = 0; nf < 4; nf++) {
                int n = bn0 + wn * 32 + nf * 8 + (lane & 3) * 2;
                float2 v{acc[mf][nf][half * 2 + 0], acc[mf][nf][half * 2 + 1]};
                *reinterpret_cast<float2*>(C + (size_t)mg * ldc + n) = v;
            }
        }
    }
}

// ---------------- logits tile 128x256, 512 thr, 3-stage (device fn) ----------------
__device__ void logits_tile(char* smem, int tt, int nt,
                            const float* __restrict__ bias, float* __restrict__ C) {
    const int tid = threadIdx.x, lane = tid & 31, wid = tid >> 5;
    const int wm = wid & 3, wn = wid >> 2;
    const int bm0 = tt * 128, bn0 = nt * 256;
    const uint32_t sbase = smem_u32(smem);
    const __half* Ah = g_Hallhi;
    const __half* Bh = g_owThi;

    float acc[2][8][4];
#pragma unroll
    for (int i = 0; i < 2; i++)
#pragma unroll
        for (int j = 0; j < 8; j++)
#pragma unroll
            for (int k = 0; k < 4; k++) acc[i][j][k] = 0.f;

    auto issue = [&](int st, int kc) {
        const int k0 = kc * 32;
        {
            int r = tid >> 2, sg = tid & 3;
            uint32_t so = sbase + (uint32_t)(st * BIG_STG + r * LDT + sg * 8) * 2;
            cp16(so, Ah + (size_t)(bm0 + r) * Hv + k0 + sg * 8);
        }
#pragma unroll
        for (int j = 0; j < 2; j++) {
            int c = tid + j * 512;
            int r = c >> 2, sg = c & 3;
            uint32_t so = sbase + (uint32_t)(st * BIG_STG + BIG_OFFB + r * LDT + sg * 8) * 2;
            cp16(so, Bh + (size_t)(bn0 + r) * Hv + k0 + sg * 8);
        }
        asm volatile("cp.async.commit_group;" ::: "memory");
    };

    const int arow = ((lane >> 3) & 1) * 8 + (lane & 7);
    const int akof = (lane >> 4) * 8;
    const int brow = ((lane >> 4) & 1) * 8 + (lane & 7);
    const int bkof = ((lane >> 3) & 1) * 8;

    constexpr int NKC = Hv / 32;
    issue(0, 0);
    issue(1, 1);
    for (int kc = 0; kc < NKC; kc++) {
        if (kc + 1 < NKC)
            asm volatile("cp.async.wait_group 1;" ::: "memory");
        else
            asm volatile("cp.async.wait_group 0;" ::: "memory");
        __syncthreads();
        if (kc + 2 < NKC) issue((kc + 2) % 3, kc + 2);
        const uint32_t bo = sbase + (uint32_t)((kc % 3) * BIG_STG) * 2;
#pragma unroll
        for (int ks = 0; ks < 2; ks++) {
            const int k0 = ks * 16;
            uint32_t bf[8][2];
#pragma unroll
            for (int p = 0; p < 4; p++) {
                uint32_t ab = bo +
                    (uint32_t)(BIG_OFFB + (wn * 64 + p * 16 + brow) * LDT + k0 + bkof) * 2;
                ldsm4(bf[2 * p][0], bf[2 * p][1], bf[2 * p + 1][0], bf[2 * p + 1][1], ab);
            }
#pragma unroll
            for (int mf = 0; mf < 2; mf++) {
                uint32_t ah4[4];
                uint32_t aa = bo + (uint32_t)((wm * 32 + mf * 16 + arow) * LDT + k0 + akof) * 2;
                ldsm4(ah4[0], ah4[1], ah4[2], ah4[3], aa);
#pragma unroll
                for (int nf = 0; nf < 8; nf++) mma16816(acc[mf][nf], ah4, bf[nf]);
            }
        }
    }
    __syncthreads();

#pragma unroll
    for (int mf = 0; mf < 2; mf++) {
#pragma unroll
        for (int half = 0; half < 2; half++) {
            int bb = wm * 32 + mf * 16 + (lane >> 2) + half * 8;
            float* dst = C + ((size_t)bb * Tv + tt) * (size_t)Vv;
#pragma unroll
            for (int nf = 0; nf < 8; nf++) {
                int n = bn0 + wn * 64 + nf * 8 + (lane & 3) * 2;
                float2 v;
                v.x = acc[mf][nf][half * 2 + 0] + bias[n];
                v.y = acc[mf][nf][half * 2 + 1] + bias[n + 1];
                *reinterpret_cast<float2*>(dst + n) = v;
            }
        }
    }
}

// ---------------- FUSED persistent kernel (512 threads) ----------------
__global__ void __launch_bounds__(THR) loop_fused(
    const float* __restrict__ fc1_b,
    const float* __restrict__ score_w, const float* __restrict__ score_b,
    const float* __restrict__ sm_w, const float* __restrict__ lm_w,
    const float* __restrict__ sm_b, const float* __restrict__ lm_b,
    float* __restrict__ wout, const float* __restrict__ out_b,
    float* __restrict__ outp) {
    extern __shared__ char smem[];
    __shared__ unsigned sh_idx;
    const int tid = threadIdx.x, lane = tid & 31, warp = tid >> 5;
    const int blk = blockIdx.x;
    unsigned tgt = 0;

    if (blk < NBLK) {
        // -------- pre-phase: h0/c0 split-K tiles (2 per block) --------
        {
#pragma unroll
            for (int q = 0; q < SK_TILES / NBLK; q++) {
                int r = blk * (SK_TILES / NBLK) + q;
                int mat = r >> 7, rem = r & 127;
                sk_tile(smem, mat ? lm_w : sm_w, mat ? g_cp : g_hp,
                        rem >> 5, (rem & 31) * 32);
                __syncthreads();
            }
        }
        gridbar(tgt);

        // -------- prologue: reduce h0/c0 for batch b = blk --------
        {
            const int b = blk;
            for (int j = tid; j < Hv; j += THR) {
                int idx = b * Hv + j;
                float h = sm_b[j], c = lm_b[j];
#pragma unroll
                for (int s = 0; s < S_HC; s++) {
                    h += g_hp[(size_t)s * Bv * Hv + idx];
                    c += g_cp[(size_t)s * Bv * Hv + idx];
                }
                g_c[idx] = c;
                g_cathi[(size_t)b * CAT + Fv + j] = __float2half_rn(h);
            }
        }
        gridbar(tgt);

        for (int t = 0; t < Tv; t++) {
            // ---------- P1: xd partials = h(fp16) @ fc1T (mma, 32 blocks) ----------
            if (blk < 32) {
                const int nt = blk & 3, ksp = blk >> 2;
                const int kbeg = ksp * (Hv / S_XD);
                float* P = g_xdp + (size_t)ksp * Bv * Av;
                mma128_tile(smem, g_cathi + Fv + kbeg, CAT,
                            g_fc1Thi + kbeg, Hv, Hv / S_XD, P, Av, 0, nt * 128);
            }
            gridbar(tgt);

            // ---------- P2: attention + softmax + context (block = batch b) ----------
            {
                float* xd_s = (float*)smem;      // 512
                float* sc = xd_s + Av;           // 64
                float* al = sc + Lv;             // 64
                float* red = al + Lv;            // 2
                const int b = blk;
                {
                    int a = tid;  // THR == Av
                    float s = fc1_b[a];
#pragma unroll
                    for (int p = 0; p < S_XD; p++) s += g_xdp[(size_t)p * Bv * Av + b * Av + a];
                    xd_s[a] = s;
                }
                __syncthreads();
                for (int l = warp; l < Lv; l += 16) {
                    const __half2* xe2 =
                        reinterpret_cast<const __half2*>(g_xench + (size_t)(b * Lv + l) * Av);
                    float s = 0.f;
                    for (int a = lane; a < Av / 2; a += 32) {
                        float2 x = __half22float2(xe2[a]);
                        s += tanh_fast(x.x + xd_s[2 * a]) * score_w[2 * a];
                        s += tanh_fast(x.y + xd_s[2 * a + 1]) * score_w[2 * a + 1];
                    }
#pragma unroll
                    for (int o = 16; o; o >>= 1) s += __shfl_xor_sync(0xFFFFFFFFu, s, o);
                    if (lane == 0) sc[l] = s + score_b[0];
                }
                __syncthreads();
                if (warp == 0) {
                    float m = fmaxf(sc[lane], sc[lane + 32]);
#pragma unroll
                    for (int o = 16; o; o >>= 1)
                        m = fmaxf(m, __shfl_xor_sync(0xFFFFFFFFu, m, o));
                    float s = expf(sc[lane] - m) + expf(sc[lane + 32] - m);
#pragma unroll
                    for (int o = 16; o; o >>= 1) s += __shfl_xor_sync(0xFFFFFFFFu, s, o);
                    if (lane == 0) { red[0] = m; red[1] = s; }
                }
                __syncthreads();
                float inv = 1.0f / red[1], smax = red[0];
                if (tid < Lv) {
                    float a = expf(sc[tid] - smax) * inv;
                    al[tid] = a;
                    if (wout) wout[((size_t)b * Tv + t) * Lv + tid] = a;
                }
                __syncthreads();
                const __half2* Xb2 =
                    reinterpret_cast<const __half2*>(g_Xhi + (size_t)b * Lv * Fv);
                __half2* cat2 = reinterpret_cast<__half2*>(g_cathi + (size_t)b * CAT);
                for (int f2 = tid; f2 < Fv / 2; f2 += THR) {
                    float sx = 0.f, sy = 0.f;
#pragma unroll
                    for (int l = 0; l < Lv; l++) {
                        float2 x = __half22float2(Xb2[(size_t)l * (Fv / 2) + f2]);
                        sx = fmaf(al[l], x.x, sx);
                        sy = fmaf(al[l], x.y, sy);
                    }
                    cat2[f2] = __floats2half2_rn(sx, sy);
                }
            }
            gridbar(tgt);

            // ---------- P3: gates partials = cat @ WcatT (1-pass fp16 mma, split-K) ----------
            {
                constexpr int KSPAN = CAT / S_GT;     // 768
                const int bn0 = (blk & 31) * 128;
                const int ksp = blk >> 5;
                const int kbeg = ksp * KSPAN;
                float* P = g_gatep + (size_t)ksp * Bv * G4H;
                mma128_tile(smem, g_cathi + kbeg, CAT, g_WcatThi + kbeg, CAT,
                            KSPAN, P, G4H, 0, bn0);
            }
            gridbar(tgt);

            // ---------- P4: gates reduce + LSTM pointwise (b = blk) ----------
            {
                const int b = blk;
                for (int j = tid; j < Hv; j += THR) {
                    int idx = b * Hv + j;
                    size_t base = (size_t)b * G4H;
                    const float* EG = g_embgate + ((size_t)t * Bv) * G4H + base;
                    float ig = EG[j], fg = EG[Hv + j], gg = EG[2 * Hv + j], og = EG[3 * Hv + j];
#pragma unroll
                    for (int s = 0; s < S_GT; s++) {
                        const float* P = g_gatep + (size_t)s * Bv * G4H + base;
                        ig += P[j];
                        fg += P[Hv + j];
                        gg += P[2 * Hv + j];
                        og += P[3 * Hv + j];
                    }
                    ig = sigmoidf_(ig);
                    fg = sigmoidf_(fg);
                    og = sigmoidf_(og);
                    gg = tanhf(gg);
                    float c2 = fg * g_c[idx] + ig * gg;
                    float h2 = og * tanhf(c2);
                    g_c[idx] = c2;
                    __half hh = __float2half_rn(h2);
                    g_cathi[(size_t)b * CAT + Fv + j] = hh;
                    g_Hallhi[((size_t)t * Bv + b) * Hv + j] = hh;
                }
            }
            gridbar(tgt);
            if (blk == 0 && tid == 0)
                asm volatile("st.release.gpu.u32 [%0], %1;"
                             :: "l"(&g_tdone), "r"((unsigned)(t + 1)) : "memory");
        }
    }

    // =================== logits tiles (128x256): work-stealing, all blocks ===================
    for (;;) {
        __syncthreads();
        if (tid == 0) sh_idx = atomicAdd(&g_tile, 1u);
        __syncthreads();
        unsigned idx = sh_idx;
        if (idx >= (unsigned)NTILES) break;
        int tt = (int)(idx / NT_N), nt = (int)(idx % NT_N);
        if (tid == 0) {
            unsigned v;
            do {
                asm volatile("ld.acquire.gpu.u32 %0, [%1];" : "=r"(v)
                             : "l"(&g_tdone) : "memory");
                if ((int)v > tt) break;
                __nanosleep(64);
            } while (true);
        }
        __syncthreads();
        logits_tile(smem, tt, nt, out_b, outp);
    }
}

// ---------------- merged preproc GEMM (x_enc + embgate), 256 thr, 2-stage ----------------
__global__ void __launch_bounds__(256) gemm_pre(
    const float* __restrict__ fc2_b,
    const float* __restrict__ b_ih, const float* __restrict__ b_hh) {
    constexpr int RBUF = 2 * 128 * LDT;
    constexpr int OFF_B = 128 * LDT;
    extern __shared__ __half smb[];
    const int tid = threadIdx.x, lane = tid & 31, wid = tid >> 5;
    const int wm = wid & 1, wn = wid >> 1;
    const uint32_t sbase = smem_u32(smb);

    const __half *Ah, *Bh;
    int lda, ldb, Kspan, bm0, bn0, ldc;
    const float *b1, *b2;
    bool hout;
    __half* Ch = nullptr;
    float* Cf = nullptr;
    if ((int)blockIdx.x < PRE_XENC) {
        int r = blockIdx.x;
        bm0 = (r >> 2) * 128;
        bn0 = (r & 3) * 128;
        Ah = g_Xhi; lda = Fv; Bh = g_fc2Thi; ldb = Fv; Kspan = Fv;
        Ch = g_xench; ldc = Av; b1 = fc2_b; b2 = nullptr; hout = true;
    } else {
        int r = blockIdx.x - PRE_XENC;
        bm0 = (r >> 5) * 128;
        bn0 = (r & 31) * 128;
        Ah = g_embxhi; lda = Ev; Bh = g_wihEThi; ldb = Ev; Kspan = Ev;
        Cf = g_embgate; ldc = G4H; b1 = b_ih; b2 = b_hh; hout = false;
    }

    float acc[4][4][4];
#pragma unroll
    for (int i = 0; i < 4; i++)
#pragma unroll
        for (int j = 0; j < 4; j++)
#pragma unroll
            for (int k = 0; k < 4; k++) acc[i][j][k] = 0.f;

    auto issue = [&](int buf, int kc) {
        const int k0 = kc * 32;
#pragma unroll
        for (int j = 0; j < 2; j++) {
            int c = tid + j * 256;
            int r = c >> 2, sg = c & 3;
            uint32_t so = sbase + (uint32_t)(buf * RBUF + r * LDT + sg * 8) * 2;
            cp16(so, Ah + (size_t)(bm0 + r) * lda + k0 + sg * 8);
            cp16(so + OFF_B * 2, Bh + (size_t)(bn0 + r) * ldb + k0 + sg * 8);
        }
        asm volatile("cp.async.commit_group;" ::: "memory");
    };

    const int arow = ((lane >> 3) & 1) * 8 + (lane & 7);
    const int akof = (lane >> 4) * 8;
    const int brow = ((lane >> 4) & 1) * 8 + (lane & 7);
    const int bkof = ((lane >> 3) & 1) * 8;

    const int NKC = Kspan / 32;
    issue(0, 0);
    for (int kc = 0; kc < NKC; kc++) {
        if (kc + 1 < NKC) {
            issue((kc + 1) & 1, kc + 1);
            asm volatile("cp.async.wait_group 1;" ::: "memory");
        } else {
            asm volatile("cp.async.wait_group 0;" ::: "memory");
        }
        __syncthreads();
        const uint32_t bo = sbase + (uint32_t)((kc & 1) * RBUF) * 2;
#pragma unroll
        for (int ks = 0; ks < 2; ks++) {
            const int k0 = ks * 16;
            uint32_t bh[4][2];
#pragma unroll
            for (int p = 0; p < 2; p++) {
                uint32_t ab = bo + (uint32_t)(OFF_B + (wn * 32 + p * 16 + brow) * LDT + k0 + bkof) * 2;
                ldsm4(bh[2 * p][0], bh[2 * p][1], bh[2 * p + 1][0], bh[2 * p + 1][1], ab);
            }
#pragma unroll
            for (int mf = 0; mf < 4; mf++) {
                uint32_t ah[4];
                uint32_t aa = bo + (uint32_t)((wm * 64 + mf * 16 + arow) * LDT + k0 + akof) * 2;
                ldsm4(ah[0], ah[1], ah[2], ah[3], aa);
#pragma unroll
                for (int nf = 0; nf < 4; nf++) mma16816(acc[mf][nf], ah, bh[nf]);
            }
        }
        __syncthreads();
    }

#pragma unroll
    for (int mf = 0; mf < 4; mf++) {
#pragma unroll
        for (int half = 0; half < 2; half++) {
            int m = bm0 + wm * 64 + mf * 16 + (lane >> 2) + half * 8;
#pragma unroll
            for (int nf = 0; nf < 4; nf++) {
                int n = bn0 + wn * 32 + nf * 8 + (lane & 3) * 2;
                float vx = acc[mf][nf][half * 2 + 0] + b1[n];
                float vy = acc[mf][nf][half * 2 + 1] + b1[n + 1];
                if (b2) { vx += b2[n]; vy += b2[n + 1]; }
                if (hout) {
                    *reinterpret_cast<__half2*>(Ch + (size_t)m * ldc + n) =
                        __floats2half2_rn(vx, vy);
                } else {
                    float2 v{vx, vy};
                    *reinterpret_cast<float2*>(Cf + (size_t)m * ldc + n) = v;
                }
            }
        }
    }
}

// ---------------- host orchestration ----------------
extern "C" void kernel_launch(void* const* d_in, const int* in_sizes, int n_in,
                              void* d_out, int out_size) {
    const float* X       = (const float*)d_in[0];
    const void*  yraw    = d_in[1];
    const float* emb     = (const float*)d_in[2];
    const float* fc1_w   = (const float*)d_in[3];
    const float* fc1_b   = (const float*)d_in[4];
    const float* fc2_w   = (const float*)d_in[5];
    const float* fc2_b   = (const float*)d_in[6];
    const float* score_w = (const float*)d_in[7];
    const float* score_b = (const float*)d_in[8];
    const float* sm_w    = (const float*)d_in[9];
    const float* sm_b    = (const float*)d_in[10];
    const float* lm_w    = (const float*)d_in[11];
    const float* lm_b    = (const float*)d_in[12];
    const float* w_ih    = (const float*)d_in[13];
    const float* b_ih    = (const float*)d_in[14];
    const float* w_hh    = (const float*)d_in[15];
    const float* b_hh    = (const float*)d_in[16];
    const float* out_w   = (const float*)d_in[17];
    const float* out_b   = (const float*)d_in[18];

    float* outp = (float*)d_out;
    const size_t osz = (size_t)Bv * Tv * Vv;
    const size_t wsz = (size_t)Bv * Tv * Lv;
    float* wout = ((size_t)out_size >= osz + wsz) ? (outp + osz) : nullptr;

    static int smem_set = 0;
    if (!smem_set) {
        cudaFuncSetAttribute(loop_fused, cudaFuncAttributeMaxDynamicSharedMemorySize,
                             SMEM_FUSED);
        cudaFuncSetAttribute(gemm_pre, cudaFuncAttributeMaxDynamicSharedMemorySize,
                             SMEM_P1);
        smem_set = 1;
    }

    // --- launch 1: all elementwise prep + all weight transposes (vectorized) ---
    {
        constexpr int NCVX = (Bv * Lv * Fv) / 4 / 256;
        constexpr int NMEAN = (Bv * Fv) / 256;
        constexpr int NGATH = (Tv * Bv * Ev) / 256;
        constexpr int NTW = (Hv / 32) * (Vv / 128) + (CAT / 32) * (G4H / 128) +
                            (Fv / 32) * (Av / 128) + (Ev / 32) * (G4H / 128) +
                            (Hv / 32) * (Av / 128);
        prep_all<<<NCVX + NMEAN + NGATH + NTW, 256>>>(
            X, yraw, emb, out_w, w_ih, w_hh, fc2_w, fc1_w);
    }
    // --- launch 2: merged preproc GEMMs (x_enc + embgate; 2 blocks/SM) ---
    gemm_pre<<<PRE_XENC + PRE_EMBG, 256, SMEM_P1>>>(fc2_b, b_ih, b_hh);

    // --- launch 3: h0/c0 split-K + persistent loop + overlapped logits ---
    loop_fused<<<NFUSE, THR, SMEM_FUSED>>>(
        fc1_b, score_w, score_b, sm_w, lm_w, sm_b, lm_b,
        wout, out_b, outp);
}